// round 2
// baseline (speedup 1.0000x reference)
#include <cuda_runtime.h>
#include <math.h>

#define B_SZ   4
#define SEQ    2048
#define DM     1024
#define ST     16
#define M_TOT  (B_SZ * SEQ)   // 8192 rows

// ---------------- scratch (static device globals; no allocation) ----------------
__device__ float g_delta[M_TOT * DM];          // 32 MB: softplus(x@Wd+bd), row-major (row, d)
__device__ float g_BC[M_TOT * 2 * ST];         // 1 MB: per row, 8 x float4 = (B[2s],B[2s+1],C[2s],C[2s+1])

// ---------------- helpers ----------------
__device__ __forceinline__ float softplus_f(float z) {
    // matches jax.nn.softplus: max(z,0) + log1p(exp(-|z|)), robust for all z
    return fmaxf(z, 0.0f) + log1pf(expf(-fabsf(z)));
}

// =================================================================================
// Kernel 1: delta = softplus(x @ Wd + bd)
// SGEMM M=8192, N=1024, K=1024. Tile 128x128, BK=16, 256 threads, 8x8 microtile.
// =================================================================================
__global__ __launch_bounds__(256) void gemm_delta_kernel(
    const float* __restrict__ x,     // (M, 1024)
    const float* __restrict__ Wd,    // (1024, 1024)
    const float* __restrict__ bd)    // (1024)
{
    __shared__ float As[16 * 132];   // transposed A tile: As[k][m], padded stride 132
    __shared__ float Bs[16 * 128];   // Bs[k][n]

    const int tid  = threadIdx.x;
    const int row0 = blockIdx.y * 128;
    const int col0 = blockIdx.x * 128;
    const int ty   = tid >> 4;       // 0..15 -> rows ty*8..ty*8+7
    const int tx   = tid & 15;       // 0..15 -> cols tx*8..tx*8+7

    float acc[8][8];
#pragma unroll
    for (int i = 0; i < 8; i++)
#pragma unroll
        for (int j = 0; j < 8; j++) acc[i][j] = 0.0f;

    for (int k0 = 0; k0 < 1024; k0 += 16) {
        // A tile: 128 rows x 16 cols = 512 float4; 2 per thread; store transposed
#pragma unroll
        for (int i = 0; i < 2; i++) {
            int idx = tid + i * 256;          // 0..511
            int r   = idx >> 2;               // 0..127
            int c4  = idx & 3;                // 0..3
            float4 v = *(const float4*)&x[(row0 + r) * DM + k0 + c4 * 4];
            As[(c4 * 4 + 0) * 132 + r] = v.x;
            As[(c4 * 4 + 1) * 132 + r] = v.y;
            As[(c4 * 4 + 2) * 132 + r] = v.z;
            As[(c4 * 4 + 3) * 132 + r] = v.w;
        }
        // B tile: 16 rows x 128 cols = 512 float4; 2 per thread
#pragma unroll
        for (int i = 0; i < 2; i++) {
            int idx = tid + i * 256;          // 0..511
            int r   = idx >> 5;               // 0..15
            int c4  = idx & 31;               // 0..31
            *(float4*)&Bs[r * 128 + c4 * 4] =
                *(const float4*)&Wd[(k0 + r) * DM + col0 + c4 * 4];
        }
        __syncthreads();

#pragma unroll
        for (int k = 0; k < 16; k++) {
            float4 a0 = *(float4*)&As[k * 132 + ty * 8];
            float4 a1 = *(float4*)&As[k * 132 + ty * 8 + 4];
            float4 b0 = *(float4*)&Bs[k * 128 + tx * 8];
            float4 b1 = *(float4*)&Bs[k * 128 + tx * 8 + 4];
            float a[8] = {a0.x, a0.y, a0.z, a0.w, a1.x, a1.y, a1.z, a1.w};
            float bv[8] = {b0.x, b0.y, b0.z, b0.w, b1.x, b1.y, b1.z, b1.w};
#pragma unroll
            for (int i = 0; i < 8; i++)
#pragma unroll
                for (int j = 0; j < 8; j++)
                    acc[i][j] = fmaf(a[i], bv[j], acc[i][j]);
        }
        __syncthreads();
    }

    // epilogue: + bias, softplus, vectorized store (two float4 per row)
    float4 bd0 = *(const float4*)&bd[col0 + tx * 8];
    float4 bd1 = *(const float4*)&bd[col0 + tx * 8 + 4];
#pragma unroll
    for (int i = 0; i < 8; i++) {
        int row = row0 + ty * 8 + i;
        float4 v0, v1;
        v0.x = softplus_f(acc[i][0] + bd0.x);
        v0.y = softplus_f(acc[i][1] + bd0.y);
        v0.z = softplus_f(acc[i][2] + bd0.z);
        v0.w = softplus_f(acc[i][3] + bd0.w);
        v1.x = softplus_f(acc[i][4] + bd1.x);
        v1.y = softplus_f(acc[i][5] + bd1.y);
        v1.z = softplus_f(acc[i][6] + bd1.z);
        v1.w = softplus_f(acc[i][7] + bd1.w);
        *(float4*)&g_delta[row * DM + col0 + tx * 8]     = v0;
        *(float4*)&g_delta[row * DM + col0 + tx * 8 + 4] = v1;
    }
}

// =================================================================================
// Kernel 2: B/C projections, interleaved output layout for the scan.
// Block = 64 rows, 256 threads, K chunked by 64.
// Output per row: 8 float4 = (B[2s], B[2s+1], C[2s], C[2s+1]) for s = 0..7
// =================================================================================
__global__ __launch_bounds__(256) void proj_bc_kernel(
    const float* __restrict__ x,     // (M, 1024)
    const float* __restrict__ Wb,    // (1024, 16)
    const float* __restrict__ bb,    // (16)
    const float* __restrict__ Wc,    // (1024, 16)
    const float* __restrict__ bc)    // (16)
{
    __shared__ float xs[64 * 65];    // padded stride 65
    __shared__ float ws[64 * 32];    // ws[k][c]: c<16 -> Wb, c>=16 -> Wc

    const int tid  = threadIdx.x;
    const int row0 = blockIdx.x * 64;
    const int rl   = tid >> 2;       // 0..63 local row
    const int q    = tid & 3;        // 0..3 -> cols q*8 .. q*8+7

    float acc[8];
#pragma unroll
    for (int j = 0; j < 8; j++) acc[j] = 0.0f;

    for (int k0 = 0; k0 < 1024; k0 += 64) {
        // x tile: 64x64, 4 float4 per thread
#pragma unroll
        for (int i = 0; i < 4; i++) {
            int idx = tid + i * 256;         // 0..1023
            int r   = idx >> 4;              // 0..63
            int c4  = idx & 15;              // 0..15
            float4 v = *(const float4*)&x[(row0 + r) * DM + k0 + c4 * 4];
            xs[r * 65 + c4 * 4 + 0] = v.x;
            xs[r * 65 + c4 * 4 + 1] = v.y;
            xs[r * 65 + c4 * 4 + 2] = v.z;
            xs[r * 65 + c4 * 4 + 3] = v.w;
        }
        // W tiles: Wb and Wc 64x16 each
        {
            int r  = tid >> 2;               // 0..63
            int c4 = tid & 3;                // 0..3
            *(float4*)&ws[r * 32 + c4 * 4]      = *(const float4*)&Wb[(k0 + r) * ST + c4 * 4];
            *(float4*)&ws[r * 32 + 16 + c4 * 4] = *(const float4*)&Wc[(k0 + r) * ST + c4 * 4];
        }
        __syncthreads();

#pragma unroll 8
        for (int k = 0; k < 64; k++) {
            float  xv = xs[rl * 65 + k];
            float4 w0 = *(float4*)&ws[k * 32 + q * 8];
            float4 w1 = *(float4*)&ws[k * 32 + q * 8 + 4];
            acc[0] = fmaf(xv, w0.x, acc[0]);
            acc[1] = fmaf(xv, w0.y, acc[1]);
            acc[2] = fmaf(xv, w0.z, acc[2]);
            acc[3] = fmaf(xv, w0.w, acc[3]);
            acc[4] = fmaf(xv, w1.x, acc[4]);
            acc[5] = fmaf(xv, w1.y, acc[5]);
            acc[6] = fmaf(xv, w1.z, acc[6]);
            acc[7] = fmaf(xv, w1.w, acc[7]);
        }
        __syncthreads();
    }

    // write interleaved: B[n] -> float4 component 0/1, C[n] -> component 2/3
    const int row = row0 + rl;
#pragma unroll
    for (int j = 0; j < 8; j++) {
        int c = q * 8 + j;                    // 0..31
        int isC = (c >= 16);
        int n = isC ? (c - 16) : c;           // 0..15
        float v = acc[j] + (isC ? bc[n] : bb[n]);
        int pos = (row * 8 + (n >> 1)) * 4 + (isC ? 2 : 0) + (n & 1);
        g_BC[pos] = v;
    }
}

// =================================================================================
// Kernel 3: sequential selective scan.
// 8 lanes per channel (b,d), 2 states (n=2s, 2s+1) per thread.
// 128 blocks x 256 threads; block covers one b and 32 d's.
// =================================================================================
__global__ __launch_bounds__(256) void scan_kernel(
    const float* __restrict__ x,       // (M, 1024)
    const float* __restrict__ A_log,   // (1024, 16)
    const float* __restrict__ D_skip,  // (1024)
    float* __restrict__ out)           // (M, 1024)
{
    const int tid = threadIdx.x;
    const int dl  = tid >> 3;          // 0..31
    const int sub = tid & 7;           // 0..7
    const int b   = blockIdx.x >> 5;   // 0..3
    const int d   = ((blockIdx.x & 31) << 5) + dl;

    const float A0  = -expf(A_log[d * ST + sub * 2]);
    const float A1  = -expf(A_log[d * ST + sub * 2 + 1]);
    const float Dsk = D_skip[d];

    float h0 = 0.0f, h1 = 0.0f;

    const int rowbase = b * SEQ;
    const float*  dp  = g_delta + rowbase * DM + d;
    const float*  xp  = x       + rowbase * DM + d;
    const float4* bcp = (const float4*)g_BC + rowbase * 8 + sub;
    float*        op  = out     + rowbase * DM + d;

#pragma unroll 4
    for (int t = 0; t < SEQ; t++) {
        float  dt = dp[t * DM];
        float  xv = xp[t * DM];
        float4 bc = bcp[t * 8];
        float e0 = __expf(dt * A0);
        float e1 = __expf(dt * A1);
        float dx = dt * xv;
        h0 = fmaf(e0, h0, dx * bc.x);
        h1 = fmaf(e1, h1, dx * bc.y);
        float p = fmaf(h0, bc.z, h1 * bc.w);
        p += __shfl_xor_sync(0xffffffffu, p, 1);
        p += __shfl_xor_sync(0xffffffffu, p, 2);
        p += __shfl_xor_sync(0xffffffffu, p, 4);
        if (sub == 0) op[t * DM] = fmaf(xv, Dsk, p);
    }
}

// =================================================================================
// launch
// =================================================================================
extern "C" void kernel_launch(void* const* d_in, const int* in_sizes, int n_in,
                              void* d_out, int out_size)
{
    const float* x      = (const float*)d_in[0];
    const float* A_log  = (const float*)d_in[1];
    const float* D_skip = (const float*)d_in[2];
    const float* Wd     = (const float*)d_in[3];
    const float* bd     = (const float*)d_in[4];
    const float* Wb     = (const float*)d_in[5];
    const float* bb     = (const float*)d_in[6];
    const float* Wc     = (const float*)d_in[7];
    const float* bc     = (const float*)d_in[8];
    float* out = (float*)d_out;

    {
        dim3 grid(DM / 128, M_TOT / 128);   // (8, 64)
        gemm_delta_kernel<<<grid, 256>>>(x, Wd, bd);
    }
    {
        proj_bc_kernel<<<M_TOT / 64, 256>>>(x, Wb, bb, Wc, bc);
    }
    {
        scan_kernel<<<B_SZ * (DM / 32), 256>>>(x, A_log, D_skip, out);
    }
}

// round 3
// speedup vs baseline: 2.0668x; 2.0668x over previous
#include <cuda_runtime.h>
#include <math.h>

#define B_SZ   4
#define SEQ    2048
#define DM     1024
#define ST     16
#define M_TOT  (B_SZ * SEQ)   // 8192 rows
#define CHUNKS 16
#define CLEN   (SEQ / CHUNKS) // 128

// ---------------- scratch (static device globals; no allocation) ----------------
__device__ float g_delta[M_TOT * DM];            // 32 MB: softplus(x@Wd+bd)
__device__ float g_BC[M_TOT * 2 * ST];           // 1 MB: per row 8 float4 = (B0,B1,C0,C1)
__device__ float g_f[B_SZ * CHUNKS * DM * ST];   // 4 MB: chunk-final states
__device__ float g_hinit[B_SZ * CHUNKS * DM * ST]; // 4 MB: chunk initial states
__device__ float g_dtsum[B_SZ * CHUNKS * DM];    // 256 KB: per-chunk sum of dt

// ---------------- helpers ----------------
__device__ __forceinline__ float softplus_f(float z) {
    return fmaxf(z, 0.0f) + log1pf(expf(-fabsf(z)));
}

// =================================================================================
// Kernel 1: delta = softplus(x @ Wd + bd)
// SGEMM M=8192, N=1024, K=1024. Tile 128x128, BK=16, 256 threads, 8x8 microtile.
// =================================================================================
__global__ __launch_bounds__(256) void gemm_delta_kernel(
    const float* __restrict__ x,     // (M, 1024)
    const float* __restrict__ Wd,    // (1024, 1024)
    const float* __restrict__ bd)    // (1024)
{
    __shared__ float As[16 * 132];   // transposed A tile: As[k][m], padded stride 132
    __shared__ float Bs[16 * 128];   // Bs[k][n]

    const int tid  = threadIdx.x;
    const int row0 = blockIdx.y * 128;
    const int col0 = blockIdx.x * 128;
    const int ty   = tid >> 4;
    const int tx   = tid & 15;

    float acc[8][8];
#pragma unroll
    for (int i = 0; i < 8; i++)
#pragma unroll
        for (int j = 0; j < 8; j++) acc[i][j] = 0.0f;

    for (int k0 = 0; k0 < 1024; k0 += 16) {
#pragma unroll
        for (int i = 0; i < 2; i++) {
            int idx = tid + i * 256;
            int r   = idx >> 2;
            int c4  = idx & 3;
            float4 v = *(const float4*)&x[(row0 + r) * DM + k0 + c4 * 4];
            As[(c4 * 4 + 0) * 132 + r] = v.x;
            As[(c4 * 4 + 1) * 132 + r] = v.y;
            As[(c4 * 4 + 2) * 132 + r] = v.z;
            As[(c4 * 4 + 3) * 132 + r] = v.w;
        }
#pragma unroll
        for (int i = 0; i < 2; i++) {
            int idx = tid + i * 256;
            int r   = idx >> 5;
            int c4  = idx & 31;
            *(float4*)&Bs[r * 128 + c4 * 4] =
                *(const float4*)&Wd[(k0 + r) * DM + col0 + c4 * 4];
        }
        __syncthreads();

#pragma unroll
        for (int k = 0; k < 16; k++) {
            float4 a0 = *(float4*)&As[k * 132 + ty * 8];
            float4 a1 = *(float4*)&As[k * 132 + ty * 8 + 4];
            float4 b0 = *(float4*)&Bs[k * 128 + tx * 8];
            float4 b1 = *(float4*)&Bs[k * 128 + tx * 8 + 4];
            float a[8] = {a0.x, a0.y, a0.z, a0.w, a1.x, a1.y, a1.z, a1.w};
            float bv[8] = {b0.x, b0.y, b0.z, b0.w, b1.x, b1.y, b1.z, b1.w};
#pragma unroll
            for (int i = 0; i < 8; i++)
#pragma unroll
                for (int j = 0; j < 8; j++)
                    acc[i][j] = fmaf(a[i], bv[j], acc[i][j]);
        }
        __syncthreads();
    }

    float4 bd0 = *(const float4*)&bd[col0 + tx * 8];
    float4 bd1 = *(const float4*)&bd[col0 + tx * 8 + 4];
#pragma unroll
    for (int i = 0; i < 8; i++) {
        int row = row0 + ty * 8 + i;
        float4 v0, v1;
        v0.x = softplus_f(acc[i][0] + bd0.x);
        v0.y = softplus_f(acc[i][1] + bd0.y);
        v0.z = softplus_f(acc[i][2] + bd0.z);
        v0.w = softplus_f(acc[i][3] + bd0.w);
        v1.x = softplus_f(acc[i][4] + bd1.x);
        v1.y = softplus_f(acc[i][5] + bd1.y);
        v1.z = softplus_f(acc[i][6] + bd1.z);
        v1.w = softplus_f(acc[i][7] + bd1.w);
        *(float4*)&g_delta[row * DM + col0 + tx * 8]     = v0;
        *(float4*)&g_delta[row * DM + col0 + tx * 8 + 4] = v1;
    }
}

// =================================================================================
// Kernel 2: B/C projections, interleaved output layout for the scan.
// =================================================================================
__global__ __launch_bounds__(256) void proj_bc_kernel(
    const float* __restrict__ x,
    const float* __restrict__ Wb, const float* __restrict__ bb,
    const float* __restrict__ Wc, const float* __restrict__ bc)
{
    __shared__ float xs[64 * 65];
    __shared__ float ws[64 * 32];

    const int tid  = threadIdx.x;
    const int row0 = blockIdx.x * 64;
    const int rl   = tid >> 2;
    const int q    = tid & 3;

    float acc[8];
#pragma unroll
    for (int j = 0; j < 8; j++) acc[j] = 0.0f;

    for (int k0 = 0; k0 < 1024; k0 += 64) {
#pragma unroll
        for (int i = 0; i < 4; i++) {
            int idx = tid + i * 256;
            int r   = idx >> 4;
            int c4  = idx & 15;
            float4 v = *(const float4*)&x[(row0 + r) * DM + k0 + c4 * 4];
            xs[r * 65 + c4 * 4 + 0] = v.x;
            xs[r * 65 + c4 * 4 + 1] = v.y;
            xs[r * 65 + c4 * 4 + 2] = v.z;
            xs[r * 65 + c4 * 4 + 3] = v.w;
        }
        {
            int r  = tid >> 2;
            int c4 = tid & 3;
            *(float4*)&ws[r * 32 + c4 * 4]      = *(const float4*)&Wb[(k0 + r) * ST + c4 * 4];
            *(float4*)&ws[r * 32 + 16 + c4 * 4] = *(const float4*)&Wc[(k0 + r) * ST + c4 * 4];
        }
        __syncthreads();

#pragma unroll 8
        for (int k = 0; k < 64; k++) {
            float  xv = xs[rl * 65 + k];
            float4 w0 = *(float4*)&ws[k * 32 + q * 8];
            float4 w1 = *(float4*)&ws[k * 32 + q * 8 + 4];
            acc[0] = fmaf(xv, w0.x, acc[0]);
            acc[1] = fmaf(xv, w0.y, acc[1]);
            acc[2] = fmaf(xv, w0.z, acc[2]);
            acc[3] = fmaf(xv, w0.w, acc[3]);
            acc[4] = fmaf(xv, w1.x, acc[4]);
            acc[5] = fmaf(xv, w1.y, acc[5]);
            acc[6] = fmaf(xv, w1.z, acc[6]);
            acc[7] = fmaf(xv, w1.w, acc[7]);
        }
        __syncthreads();
    }

    const int row = row0 + rl;
#pragma unroll
    for (int j = 0; j < 8; j++) {
        int c = q * 8 + j;
        int isC = (c >= 16);
        int n = isC ? (c - 16) : c;
        float v = acc[j] + (isC ? bc[n] : bb[n]);
        int pos = (row * 8 + (n >> 1)) * 4 + (isC ? 2 : 0) + (n & 1);
        g_BC[pos] = v;
    }
}

// =================================================================================
// Kernel 3a / 3c: chunk-local scan. FINAL=false -> emit chunk summary (f, sum dt).
// FINAL=true -> seeded with g_hinit, emit outputs y.
// Block = (one b, one chunk, 32 d's) x 8 state-lanes = 256 threads. Grid = 2048.
// =================================================================================
template<bool FINAL>
__global__ __launch_bounds__(256) void scan_chunk_kernel(
    const float* __restrict__ x,       // (M, 1024)
    const float* __restrict__ A_log,   // (1024, 16)
    const float* __restrict__ D_skip,  // (1024)
    float* __restrict__ out)           // (M, 1024)
{
    const int tid = threadIdx.x;
    const int dl  = tid >> 3;              // 0..31
    const int sub = tid & 7;               // 0..7  (states 2*sub, 2*sub+1)
    const int dg  = blockIdx.x & 31;       // d-group
    const int c   = (blockIdx.x >> 5) & (CHUNKS - 1);
    const int b   = blockIdx.x >> 9;       // 5 + log2(CHUNKS)
    const int d   = dg * 32 + dl;

    const float A0 = -expf(A_log[d * ST + sub * 2]);
    const float A1 = -expf(A_log[d * ST + sub * 2 + 1]);

    const int rowbase = b * SEQ + c * CLEN;
    const float*  dp  = g_delta + rowbase * DM + d;
    const float*  xp  = x       + rowbase * DM + d;
    const float4* bcp = (const float4*)g_BC + rowbase * 8 + sub;
    const int sidx    = ((b * CHUNKS + c) * DM + d) * ST + sub * 2;

    float h0, h1;
    float Dsk = 0.0f;
    float* op = 0;
    if (FINAL) {
        float2 hv = *(const float2*)&g_hinit[sidx];
        h0 = hv.x; h1 = hv.y;
        Dsk = D_skip[d];
        op  = out + rowbase * DM + d;
    } else {
        h0 = 0.0f; h1 = 0.0f;
    }
    float dts = 0.0f;

#pragma unroll 4
    for (int t = 0; t < CLEN; t++) {
        float  dt = dp[t * DM];
        float  xv = xp[t * DM];
        float4 bc = bcp[t * 8];
        float e0 = __expf(dt * A0);
        float e1 = __expf(dt * A1);
        float dx = dt * xv;
        h0 = fmaf(e0, h0, dx * bc.x);
        h1 = fmaf(e1, h1, dx * bc.y);
        if (FINAL) {
            float p = fmaf(h0, bc.z, h1 * bc.w);
            p += __shfl_xor_sync(0xffffffffu, p, 1);
            p += __shfl_xor_sync(0xffffffffu, p, 2);
            p += __shfl_xor_sync(0xffffffffu, p, 4);
            if (sub == 0) op[t * DM] = fmaf(xv, Dsk, p);
        } else {
            dts += dt;
        }
    }

    if (!FINAL) {
        *(float2*)&g_f[sidx] = make_float2(h0, h1);
        if (sub == 0) g_dtsum[(b * CHUNKS + c) * DM + d] = dts;
    }
}

// =================================================================================
// Kernel 3b: sequential combine across chunks. One thread per (b,d,n).
// H_c = exp(A * dtsum_c) * H_{c-1} + f_c ; g_hinit[c] = H_{c-1} (H_{-1} = 0).
// =================================================================================
__global__ __launch_bounds__(256) void scan_combine_kernel(
    const float* __restrict__ A_log)
{
    const int tid = blockIdx.x * blockDim.x + threadIdx.x;  // 0..65535
    const int n = tid & 15;
    const int d = (tid >> 4) & (DM - 1);
    const int b = tid >> 14;

    const float A = -expf(A_log[d * ST + n]);
    float H = 0.0f;
#pragma unroll
    for (int c = 0; c < CHUNKS; c++) {
        const int base = (b * CHUNKS + c) * DM + d;
        g_hinit[base * ST + n] = H;
        float P = __expf(A * g_dtsum[base]);
        H = fmaf(P, H, g_f[base * ST + n]);
    }
}

// =================================================================================
// launch
// =================================================================================
extern "C" void kernel_launch(void* const* d_in, const int* in_sizes, int n_in,
                              void* d_out, int out_size)
{
    const float* x      = (const float*)d_in[0];
    const float* A_log  = (const float*)d_in[1];
    const float* D_skip = (const float*)d_in[2];
    const float* Wd     = (const float*)d_in[3];
    const float* bd     = (const float*)d_in[4];
    const float* Wb     = (const float*)d_in[5];
    const float* bb     = (const float*)d_in[6];
    const float* Wc     = (const float*)d_in[7];
    const float* bc     = (const float*)d_in[8];
    float* out = (float*)d_out;

    {
        dim3 grid(DM / 128, M_TOT / 128);   // (8, 64)
        gemm_delta_kernel<<<grid, 256>>>(x, Wd, bd);
    }
    proj_bc_kernel<<<M_TOT / 64, 256>>>(x, Wb, bb, Wc, bc);

    const int scan_grid = B_SZ * CHUNKS * (DM / 32);   // 2048
    scan_chunk_kernel<false><<<scan_grid, 256>>>(x, A_log, D_skip, out);
    scan_combine_kernel<<<(B_SZ * DM * ST) / 256, 256>>>(A_log);
    scan_chunk_kernel<true><<<scan_grid, 256>>>(x, A_log, D_skip, out);
}

// round 5
// speedup vs baseline: 2.8435x; 1.3758x over previous
#include <cuda_runtime.h>
#include <cuda_bf16.h>
#include <math.h>
#include <stdint.h>

#define B_SZ   4
#define SEQ    2048
#define DM     1024
#define ST     16
#define M_TOT  (B_SZ * SEQ)   // 8192 rows
#define CHUNKS 32
#define CLEN   (SEQ / CHUNKS) // 64

// ---------------- scratch (static device globals; no allocation) ----------------
__device__ float g_delta[M_TOT * DM];              // 32 MB
__device__ float g_BC[M_TOT * 2 * ST];             // 1 MB
__device__ float g_f[B_SZ * CHUNKS * DM * ST];     // 8 MB
__device__ float g_hinit[B_SZ * CHUNKS * DM * ST]; // 8 MB
__device__ float g_dtsum[B_SZ * CHUNKS * DM];      // 512 KB
__device__ __nv_bfloat16 g_xhi[M_TOT * DM];        // 16 MB
__device__ __nv_bfloat16 g_xlo[M_TOT * DM];        // 16 MB
__device__ __nv_bfloat16 g_wthi[DM * DM];          // 2 MB  (n,k)-major
__device__ __nv_bfloat16 g_wtlo[DM * DM];          // 2 MB

// ---------------- helpers ----------------
__device__ __forceinline__ float softplus_f(float z) {
    return fmaxf(z, 0.0f) + log1pf(expf(-fabsf(z)));
}
__device__ __forceinline__ uint32_t smem_u32(const void* p) {
    uint32_t a;
    asm("{ .reg .u64 t; cvta.to.shared.u64 t, %1; cvt.u32.u64 %0, t; }" : "=r"(a) : "l"(p));
    return a;
}

#define CP_ASYNC16(dst, src) \
    asm volatile("cp.async.cg.shared.global [%0], [%1], 16;" :: "r"(dst), "l"(src))
#define CP_COMMIT()  asm volatile("cp.async.commit_group;" ::: "memory")
#define CP_WAIT(N)   asm volatile("cp.async.wait_group %0;" :: "n"(N) : "memory")

__device__ __forceinline__ void ldsm_x4(uint32_t& r0, uint32_t& r1, uint32_t& r2, uint32_t& r3,
                                        uint32_t addr) {
    asm volatile("ldmatrix.sync.aligned.m8n8.x4.shared.b16 {%0,%1,%2,%3}, [%4];"
                 : "=r"(r0), "=r"(r1), "=r"(r2), "=r"(r3) : "r"(addr));
}
__device__ __forceinline__ void ldsm_x2(uint32_t& r0, uint32_t& r1, uint32_t addr) {
    asm volatile("ldmatrix.sync.aligned.m8n8.x2.shared.b16 {%0,%1}, [%2];"
                 : "=r"(r0), "=r"(r1) : "r"(addr));
}
__device__ __forceinline__ void mma_bf16(float& c0, float& c1, float& c2, float& c3,
                                         uint32_t a0, uint32_t a1, uint32_t a2, uint32_t a3,
                                         uint32_t b0, uint32_t b1) {
    asm volatile(
        "mma.sync.aligned.m16n8k16.row.col.f32.bf16.bf16.f32 "
        "{%0,%1,%2,%3}, {%4,%5,%6,%7}, {%8,%9}, {%0,%1,%2,%3};"
        : "+f"(c0), "+f"(c1), "+f"(c2), "+f"(c3)
        : "r"(a0), "r"(a1), "r"(a2), "r"(a3), "r"(b0), "r"(b1));
}

// =================================================================================
// Kernel 0a: convert x -> bf16 hi/lo
// =================================================================================
__global__ __launch_bounds__(256) void convert_x_kernel(const float* __restrict__ x)
{
    const int i = blockIdx.x * 256 + threadIdx.x;     // over 2M float4s
    float4 v = ((const float4*)x)[i];
    __nv_bfloat16 hx = __float2bfloat16_rn(v.x);
    __nv_bfloat16 hy = __float2bfloat16_rn(v.y);
    __nv_bfloat16 hz = __float2bfloat16_rn(v.z);
    __nv_bfloat16 hw = __float2bfloat16_rn(v.w);
    __nv_bfloat162* phi = (__nv_bfloat162*)g_xhi;
    __nv_bfloat162* plo = (__nv_bfloat162*)g_xlo;
    phi[i * 2 + 0] = __nv_bfloat162(hx, hy);
    phi[i * 2 + 1] = __nv_bfloat162(hz, hw);
    plo[i * 2 + 0] = __nv_bfloat162(__float2bfloat16_rn(v.x - __bfloat162float(hx)),
                                    __float2bfloat16_rn(v.y - __bfloat162float(hy)));
    plo[i * 2 + 1] = __nv_bfloat162(__float2bfloat16_rn(v.z - __bfloat162float(hz)),
                                    __float2bfloat16_rn(v.w - __bfloat162float(hw)));
}

// =================================================================================
// Kernel 0b: transpose+convert Wd -> Wt_hi/lo ((n,k)-major bf16)
// =================================================================================
__global__ __launch_bounds__(256) void transpose_w_kernel(const float* __restrict__ Wd)
{
    __shared__ float tile[32][33];
    const int x0 = blockIdx.x * 32;
    const int y0 = blockIdx.y * 32;
    const int tx = threadIdx.x & 31;
    const int ty = threadIdx.x >> 5;   // 0..7
#pragma unroll
    for (int i = 0; i < 32; i += 8)
        tile[ty + i][tx] = Wd[(y0 + ty + i) * DM + x0 + tx];
    __syncthreads();
#pragma unroll
    for (int i = 0; i < 32; i += 8) {
        float v = tile[tx][ty + i];
        __nv_bfloat16 h = __float2bfloat16_rn(v);
        g_wthi[(x0 + ty + i) * DM + y0 + tx] = h;
        g_wtlo[(x0 + ty + i) * DM + y0 + tx] = __float2bfloat16_rn(v - __bfloat162float(h));
    }
}

// =================================================================================
// Kernel 1: delta = softplus(x @ Wd + bd) via mma.sync bf16 3-term split.
// CTA 128x128, BK=32, 8 warps (2m x 4n), warp tile 64x32, cp.async double buffer.
// SMEM tile rows padded to 80B (32 bf16 data + 16B pad) -> ldmatrix conflict-free.
// =================================================================================
#define ROWB   80
#define T_A_HI 0
#define T_A_LO 10240
#define T_B_HI 20480
#define T_B_LO 30720
#define BUFS   40960
#define GS_TOTAL (2 * BUFS)  // 81920
#define BK     32
#define NSLAB  (DM / BK)     // 32

__device__ __forceinline__ void gemm_load_slab(uint32_t sb, int buf, int row0, int col0,
                                               int k0, int tid)
{
    const uint32_t base = sb + buf * BUFS;
#pragma unroll
    for (int t = 0; t < 2; t++) {
        int op  = tid + t * 256;       // 0..511
        int row = op >> 2;             // 0..127
        int seg = op & 3;              // 0..3 (16B each)
        uint32_t doff = row * ROWB + seg * 16;
        const __nv_bfloat16* sa = &g_xhi[(row0 + row) * DM + k0 + seg * 8];
        CP_ASYNC16(base + T_A_HI + doff, sa);
        const __nv_bfloat16* sal = &g_xlo[(row0 + row) * DM + k0 + seg * 8];
        CP_ASYNC16(base + T_A_LO + doff, sal);
        const __nv_bfloat16* sbh = &g_wthi[(col0 + row) * DM + k0 + seg * 8];
        CP_ASYNC16(base + T_B_HI + doff, sbh);
        const __nv_bfloat16* sbl = &g_wtlo[(col0 + row) * DM + k0 + seg * 8];
        CP_ASYNC16(base + T_B_LO + doff, sbl);
    }
}

__global__ __launch_bounds__(256) void gemm_delta_mma(const float* __restrict__ bd)
{
    extern __shared__ char smem[];
    const uint32_t sb = smem_u32(smem);
    const int tid  = threadIdx.x;
    const int lane = tid & 31;
    const int warp = tid >> 5;
    const int wm   = warp & 1;         // 0..1 -> m offset wm*64
    const int wn   = warp >> 1;        // 0..3 -> n offset wn*32
    const int row0 = blockIdx.y * 128;
    const int col0 = blockIdx.x * 128;

    float acc[4][4][4];
#pragma unroll
    for (int i = 0; i < 4; i++)
#pragma unroll
        for (int j = 0; j < 4; j++)
#pragma unroll
            for (int k = 0; k < 4; k++) acc[i][j][k] = 0.0f;

    // ldmatrix per-lane addressing
    const int rlA = (lane & 7) + 8 * ((lane >> 3) & 1);   // row within 16-row frag
    const int cbA = (lane >> 4) * 16;                     // col byte (k 8-15 half)
    const int rlB = lane & 7;                             // n row within 8
    const int cbB = ((lane >> 3) & 1) * 16;               // k-half byte offset

    gemm_load_slab(sb, 0, row0, col0, 0, tid);
    CP_COMMIT();

    for (int s = 0; s < NSLAB; s++) {
        if (s + 1 < NSLAB) {
            gemm_load_slab(sb, (s + 1) & 1, row0, col0, (s + 1) * BK, tid);
            CP_COMMIT();
            CP_WAIT(1);
        } else {
            CP_WAIT(0);
        }
        __syncthreads();

        const uint32_t bufb = sb + (s & 1) * BUFS;
        const uint32_t aHi = bufb + T_A_HI + (wm * 64) * ROWB;
        const uint32_t aLo = bufb + T_A_LO + (wm * 64) * ROWB;
        const uint32_t bHi = bufb + T_B_HI + (wn * 32) * ROWB;
        const uint32_t bLo = bufb + T_B_LO + (wn * 32) * ROWB;

#pragma unroll
        for (int ks = 0; ks < 2; ks++) {
            const int ksb = ks * 32;   // 16 elems * 2B
            uint32_t ah[4][4], al[4][4];
#pragma unroll
            for (int mf = 0; mf < 4; mf++) {
                uint32_t ao = (mf * 16 + rlA) * ROWB + ksb + cbA;
                ldsm_x4(ah[mf][0], ah[mf][1], ah[mf][2], ah[mf][3], aHi + ao);
                ldsm_x4(al[mf][0], al[mf][1], al[mf][2], al[mf][3], aLo + ao);
            }
            uint32_t bh[4][2], bl[4][2];
#pragma unroll
            for (int nf = 0; nf < 4; nf++) {
                uint32_t bo = (nf * 8 + rlB) * ROWB + ksb + cbB;
                ldsm_x2(bh[nf][0], bh[nf][1], bHi + bo);
                ldsm_x2(bl[nf][0], bl[nf][1], bLo + bo);
            }
#pragma unroll
            for (int mf = 0; mf < 4; mf++)
#pragma unroll
                for (int nf = 0; nf < 4; nf++) {
                    float* c = acc[mf][nf];
                    mma_bf16(c[0], c[1], c[2], c[3],
                             ah[mf][0], ah[mf][1], ah[mf][2], ah[mf][3],
                             bh[nf][0], bh[nf][1]);
                    mma_bf16(c[0], c[1], c[2], c[3],
                             ah[mf][0], ah[mf][1], ah[mf][2], ah[mf][3],
                             bl[nf][0], bl[nf][1]);
                    mma_bf16(c[0], c[1], c[2], c[3],
                             al[mf][0], al[mf][1], al[mf][2], al[mf][3],
                             bh[nf][0], bh[nf][1]);
                }
        }
        __syncthreads();
    }

    // epilogue
    const int g   = lane >> 2;
    const int tig = lane & 3;
#pragma unroll
    for (int nf = 0; nf < 4; nf++) {
        const int col = col0 + wn * 32 + nf * 8 + tig * 2;
        const float b0v = bd[col];
        const float b1v = bd[col + 1];
#pragma unroll
        for (int mf = 0; mf < 4; mf++) {
            const int row = row0 + wm * 64 + mf * 16 + g;
            float* c = acc[mf][nf];
            float2 v0, v1;
            v0.x = softplus_f(c[0] + b0v);
            v0.y = softplus_f(c[1] + b1v);
            v1.x = softplus_f(c[2] + b0v);
            v1.y = softplus_f(c[3] + b1v);
            *(float2*)&g_delta[row * DM + col]       = v0;
            *(float2*)&g_delta[(row + 8) * DM + col] = v1;
        }
    }
}

// =================================================================================
// Kernel 2: B/C projections, interleaved output layout for the scan.
// =================================================================================
__global__ __launch_bounds__(256) void proj_bc_kernel(
    const float* __restrict__ x,
    const float* __restrict__ Wb, const float* __restrict__ bb,
    const float* __restrict__ Wc, const float* __restrict__ bc)
{
    __shared__ float xs[64 * 65];
    __shared__ float ws[64 * 32];

    const int tid  = threadIdx.x;
    const int row0 = blockIdx.x * 64;
    const int rl   = tid >> 2;
    const int q    = tid & 3;

    float acc[8];
#pragma unroll
    for (int j = 0; j < 8; j++) acc[j] = 0.0f;

    for (int k0 = 0; k0 < 1024; k0 += 64) {
#pragma unroll
        for (int i = 0; i < 4; i++) {
            int idx = tid + i * 256;
            int r   = idx >> 4;
            int c4  = idx & 15;
            float4 v = *(const float4*)&x[(row0 + r) * DM + k0 + c4 * 4];
            xs[r * 65 + c4 * 4 + 0] = v.x;
            xs[r * 65 + c4 * 4 + 1] = v.y;
            xs[r * 65 + c4 * 4 + 2] = v.z;
            xs[r * 65 + c4 * 4 + 3] = v.w;
        }
        {
            int r  = tid >> 2;
            int c4 = tid & 3;
            *(float4*)&ws[r * 32 + c4 * 4]      = *(const float4*)&Wb[(k0 + r) * ST + c4 * 4];
            *(float4*)&ws[r * 32 + 16 + c4 * 4] = *(const float4*)&Wc[(k0 + r) * ST + c4 * 4];
        }
        __syncthreads();

#pragma unroll 8
        for (int k = 0; k < 64; k++) {
            float  xv = xs[rl * 65 + k];
            float4 w0 = *(float4*)&ws[k * 32 + q * 8];
            float4 w1 = *(float4*)&ws[k * 32 + q * 8 + 4];
            acc[0] = fmaf(xv, w0.x, acc[0]);
            acc[1] = fmaf(xv, w0.y, acc[1]);
            acc[2] = fmaf(xv, w0.z, acc[2]);
            acc[3] = fmaf(xv, w0.w, acc[3]);
            acc[4] = fmaf(xv, w1.x, acc[4]);
            acc[5] = fmaf(xv, w1.y, acc[5]);
            acc[6] = fmaf(xv, w1.z, acc[6]);
            acc[7] = fmaf(xv, w1.w, acc[7]);
        }
        __syncthreads();
    }

    const int row = row0 + rl;
#pragma unroll
    for (int j = 0; j < 8; j++) {
        int c = q * 8 + j;
        int isC = (c >= 16);
        int n = isC ? (c - 16) : c;
        float v = acc[j] + (isC ? bc[n] : bb[n]);
        int pos = (row * 8 + (n >> 1)) * 4 + (isC ? 2 : 0) + (n & 1);
        g_BC[pos] = v;
    }
}

// =================================================================================
// Kernel 3a / 3c: chunk-local scan.
// =================================================================================
template<bool FINAL>
__global__ __launch_bounds__(256) void scan_chunk_kernel(
    const float* __restrict__ x,
    const float* __restrict__ A_log,
    const float* __restrict__ D_skip,
    float* __restrict__ out)
{
    const int tid = threadIdx.x;
    const int dl  = tid >> 3;
    const int sub = tid & 7;
    const int dg  = blockIdx.x & 31;
    const int c   = (blockIdx.x >> 5) & (CHUNKS - 1);
    const int b   = blockIdx.x >> 10;
    const int d   = dg * 32 + dl;

    const float A0 = -expf(A_log[d * ST + sub * 2]);
    const float A1 = -expf(A_log[d * ST + sub * 2 + 1]);

    const int rowbase = b * SEQ + c * CLEN;
    const float*  dp  = g_delta + rowbase * DM + d;
    const float*  xp  = x       + rowbase * DM + d;
    const float4* bcp = (const float4*)g_BC + rowbase * 8 + sub;
    const int sidx    = ((b * CHUNKS + c) * DM + d) * ST + sub * 2;

    float h0, h1;
    float Dsk = 0.0f;
    float* op = 0;
    if (FINAL) {
        float2 hv = *(const float2*)&g_hinit[sidx];
        h0 = hv.x; h1 = hv.y;
        Dsk = D_skip[d];
        op  = out + rowbase * DM + d;
    } else {
        h0 = 0.0f; h1 = 0.0f;
    }
    float dts = 0.0f;

#pragma unroll 4
    for (int t = 0; t < CLEN; t++) {
        float  dt = dp[t * DM];
        float  xv = xp[t * DM];
        float4 bc = bcp[t * 8];
        float e0 = __expf(dt * A0);
        float e1 = __expf(dt * A1);
        float dx = dt * xv;
        h0 = fmaf(e0, h0, dx * bc.x);
        h1 = fmaf(e1, h1, dx * bc.y);
        if (FINAL) {
            float p = fmaf(h0, bc.z, h1 * bc.w);
            p += __shfl_xor_sync(0xffffffffu, p, 1);
            p += __shfl_xor_sync(0xffffffffu, p, 2);
            p += __shfl_xor_sync(0xffffffffu, p, 4);
            if (sub == 0) op[t * DM] = fmaf(xv, Dsk, p);
        } else {
            dts += dt;
        }
    }

    if (!FINAL) {
        *(float2*)&g_f[sidx] = make_float2(h0, h1);
        if (sub == 0) g_dtsum[(b * CHUNKS + c) * DM + d] = dts;
    }
}

// =================================================================================
// Kernel 3b: sequential combine across chunks.
// =================================================================================
__global__ __launch_bounds__(256) void scan_combine_kernel(
    const float* __restrict__ A_log)
{
    const int tid = blockIdx.x * blockDim.x + threadIdx.x;
    const int n = tid & 15;
    const int d = (tid >> 4) & (DM - 1);
    const int b = tid >> 14;

    const float A = -expf(A_log[d * ST + n]);
    float H = 0.0f;
#pragma unroll
    for (int c = 0; c < CHUNKS; c++) {
        const int base = (b * CHUNKS + c) * DM + d;
        g_hinit[base * ST + n] = H;
        float P = __expf(A * g_dtsum[base]);
        H = fmaf(P, H, g_f[base * ST + n]);
    }
}

// =================================================================================
// launch
// =================================================================================
extern "C" void kernel_launch(void* const* d_in, const int* in_sizes, int n_in,
                              void* d_out, int out_size)
{
    const float* x      = (const float*)d_in[0];
    const float* A_log  = (const float*)d_in[1];
    const float* D_skip = (const float*)d_in[2];
    const float* Wd     = (const float*)d_in[3];
    const float* bd     = (const float*)d_in[4];
    const float* Wb     = (const float*)d_in[5];
    const float* bb     = (const float*)d_in[6];
    const float* Wc     = (const float*)d_in[7];
    const float* bc     = (const float*)d_in[8];
    float* out = (float*)d_out;

    cudaFuncSetAttribute(gemm_delta_mma, cudaFuncAttributeMaxDynamicSharedMemorySize, GS_TOTAL);

    convert_x_kernel<<<(M_TOT * DM / 4) / 256, 256>>>(x);
    {
        dim3 tgrid(DM / 32, DM / 32);
        transpose_w_kernel<<<tgrid, 256>>>(Wd);
    }
    {
        dim3 grid(DM / 128, M_TOT / 128);   // (8, 64)
        gemm_delta_mma<<<grid, 256, GS_TOTAL>>>(bd);
    }
    proj_bc_kernel<<<M_TOT / 64, 256>>>(x, Wb, bb, Wc, bc);

    const int scan_grid = B_SZ * CHUNKS * (DM / 32);   // 4096
    scan_chunk_kernel<false><<<scan_grid, 256>>>(x, A_log, D_skip, out);
    scan_combine_kernel<<<(B_SZ * DM * ST) / 256, 256>>>(A_log);
    scan_chunk_kernel<true><<<scan_grid, 256>>>(x, A_log, D_skip, out);
}